// round 1
// baseline (speedup 1.0000x reference)
#include <cuda_runtime.h>
#include <math_constants.h>

#define Bn 16
#define Kn 256
#define Zn 128
#define Hn 128
#define BK (Bn*Kn)

// ---------------- device scratch (no allocations allowed) ----------------
__device__ float g_W1t[Zn*Zn];      // W1 transposed: [k][c_out]
__device__ float g_W2t[Zn*Zn];
__device__ float g_Wut[2*Zn*Hn];    // Wu transposed: [k][h]
__device__ float g_m1z[BK*Zn];
__device__ float g_m2z[BK*Zn];
__device__ float g_m[BK*Zn];

// ---------------- prep: transpose weights for coalesced k-major reads ----
__global__ void prep_kernel(const float* __restrict__ W1,
                            const float* __restrict__ W2,
                            const float* __restrict__ Wu) {
    int stride = gridDim.x * blockDim.x;
    int t0 = blockIdx.x * blockDim.x + threadIdx.x;
    for (int idx = t0; idx < Zn * Zn; idx += stride) {
        int k = idx / Zn, c = idx % Zn;
        g_W1t[idx] = W1[c * Zn + k];
        g_W2t[idx] = W2[c * Zn + k];
    }
    for (int idx = t0; idx < 2 * Zn * Hn; idx += stride) {
        int k = idx / Hn, h = idx % Hn;
        g_Wut[idx] = Wu[h * (2 * Zn) + k];
    }
}

// ---------------- K1: m1z = z@W1^T + b1, m2z = z@W2^T + b2 ----------------
// 8 rows per block, 128 threads (lane = output channel).
#define R1 8
__global__ __launch_bounds__(128)
void linear12_kernel(const float* __restrict__ z,
                     const float* __restrict__ b1,
                     const float* __restrict__ b2) {
    __shared__ float zsT[Zn * 12];   // transposed z tile, pad 12 (48B rows, 16B aligned)
    int r0 = blockIdx.x * R1;
    int c = threadIdx.x;
    const float* zrow = z + (size_t)r0 * Zn;
#pragma unroll
    for (int i = 0; i < R1; i++) zsT[c * 12 + i] = zrow[(size_t)i * Zn + c];
    __syncthreads();

    float acc1[R1], acc2[R1];
#pragma unroll
    for (int i = 0; i < R1; i++) { acc1[i] = 0.f; acc2[i] = 0.f; }

#pragma unroll 4
    for (int k = 0; k < Zn; k++) {
        float w1 = g_W1t[k * Zn + c];
        float w2 = g_W2t[k * Zn + c];
        float4 za = *reinterpret_cast<const float4*>(&zsT[k * 12]);
        float4 zb = *reinterpret_cast<const float4*>(&zsT[k * 12 + 4]);
        float zv[R1] = {za.x, za.y, za.z, za.w, zb.x, zb.y, zb.z, zb.w};
#pragma unroll
        for (int i = 0; i < R1; i++) {
            acc1[i] = fmaf(zv[i], w1, acc1[i]);
            acc2[i] = fmaf(zv[i], w2, acc2[i]);
        }
    }
    float bb1 = b1[c], bb2 = b2[c];
#pragma unroll
    for (int i = 0; i < R1; i++) {
        g_m1z[(size_t)(r0 + i) * Zn + c] = acc1[i] + bb1;
        g_m2z[(size_t)(r0 + i) * Zn + c] = acc2[i] + bb2;
    }
}

// ---------------- K2: masked column max + fused message relu --------------
// m[b,i,c] = relu(m1z[b,i,c] + max_{j: P[b,j,i]!=0} m2z[b,j,c])
// Mask stored as float {0, -inf} in smem so inner loop is FADD+FMNMX
// (dual-issues on fma/alu pipes). Block = (b, 32-wide i tile), 256 threads
// = 2 i-groups x 128 c-lanes, 16 accumulators per thread.
#define IT 32
__global__ __launch_bounds__(256)
void maxmsg_kernel(const int* __restrict__ P) {
    __shared__ float maskf[Kn * IT];   // 32 KB: [j][ii] in {0, -inf}
    int b = blockIdx.y;
    int i0 = blockIdx.x * IT;
    int tid = threadIdx.x;

    const int* Pb = P + (size_t)b * Kn * Kn + i0;
#pragma unroll
    for (int it = 0; it < (Kn * IT) / 256; it++) {
        int e = tid + it * 256;
        int j = e >> 5, ii = e & 31;
        maskf[e] = Pb[(size_t)j * Kn + ii] ? 0.f : -CUDART_INF_F;
    }
    __syncthreads();

    int g = tid >> 7;        // i-group 0/1
    int c = tid & 127;       // channel lane
    const float* m2row = g_m2z + (size_t)b * Kn * Zn + c;

    float acc[16];
#pragma unroll
    for (int i = 0; i < 16; i++) acc[i] = -CUDART_INF_F;

#pragma unroll 2
    for (int j = 0; j < Kn; j++) {
        float v = m2row[(size_t)j * Zn];
        const float4* mr = reinterpret_cast<const float4*>(&maskf[j * IT + g * 16]);
        float4 m0 = mr[0], m1 = mr[1], m2 = mr[2], m3 = mr[3];
        float mv[16] = {m0.x, m0.y, m0.z, m0.w, m1.x, m1.y, m1.z, m1.w,
                        m2.x, m2.y, m2.z, m2.w, m3.x, m3.y, m3.z, m3.w};
#pragma unroll
        for (int i = 0; i < 16; i++) acc[i] = fmaxf(acc[i], v + mv[i]);
    }

    const float* m1row = g_m1z + (size_t)b * Kn * Zn + (size_t)(i0 + g * 16) * Zn + c;
    float* mrow       = g_m   + (size_t)b * Kn * Zn + (size_t)(i0 + g * 16) * Zn + c;
#pragma unroll
    for (int i = 0; i < 16; i++) {
        float val = m1row[(size_t)i * Zn] + acc[i];
        mrow[(size_t)i * Zn] = fmaxf(val, 0.f);
    }
}

// ---------------- K3: out = relu([z, m] @ Wu^T + bu) ----------------------
#define R3 8
__global__ __launch_bounds__(128)
void final_kernel(const float* __restrict__ z,
                  const float* __restrict__ bu,
                  float* __restrict__ out) {
    __shared__ float xsT[(2 * Zn) * 12];   // 12 KB
    int r0 = blockIdx.x * R3;
    int c = threadIdx.x;
    const float* zrow = z   + (size_t)r0 * Zn;
    const float* mrow = g_m + (size_t)r0 * Zn;
#pragma unroll
    for (int i = 0; i < R3; i++) {
        xsT[c * 12 + i]            = zrow[(size_t)i * Zn + c];
        xsT[(Zn + c) * 12 + i]     = mrow[(size_t)i * Zn + c];
    }
    __syncthreads();

    float acc[R3];
#pragma unroll
    for (int i = 0; i < R3; i++) acc[i] = 0.f;

#pragma unroll 4
    for (int k = 0; k < 2 * Zn; k++) {
        float w = g_Wut[k * Hn + c];
        float4 xa = *reinterpret_cast<const float4*>(&xsT[k * 12]);
        float4 xb = *reinterpret_cast<const float4*>(&xsT[k * 12 + 4]);
        float xv[R3] = {xa.x, xa.y, xa.z, xa.w, xb.x, xb.y, xb.z, xb.w};
#pragma unroll
        for (int i = 0; i < R3; i++) acc[i] = fmaf(xv[i], w, acc[i]);
    }
    float bb = bu[c];
#pragma unroll
    for (int i = 0; i < R3; i++)
        out[(size_t)(r0 + i) * Hn + c] = fmaxf(acc[i] + bb, 0.f);
}

// --------------------------------------------------------------------------
extern "C" void kernel_launch(void* const* d_in, const int* in_sizes, int n_in,
                              void* d_out, int out_size) {
    const float* z  = (const float*)d_in[0];
    const int*   P  = (const int*)  d_in[1];
    const float* W1 = (const float*)d_in[2];
    const float* b1 = (const float*)d_in[3];
    const float* W2 = (const float*)d_in[4];
    const float* b2 = (const float*)d_in[5];
    const float* Wu = (const float*)d_in[6];
    const float* bu = (const float*)d_in[7];
    float* out = (float*)d_out;

    prep_kernel<<<64, 256>>>(W1, W2, Wu);
    linear12_kernel<<<BK / R1, 128>>>(z, b1, b2);
    dim3 g2(Kn / IT, Bn);
    maxmsg_kernel<<<g2, 256>>>(P);
    final_kernel<<<BK / R3, 128>>>(z, bu, out);
}

// round 2
// speedup vs baseline: 1.7754x; 1.7754x over previous
#include <cuda_runtime.h>
#include <math_constants.h>

#define Bn 16
#define Kn 256
#define Zn 128
#define Hn 128
#define BK (Bn*Kn)

// ---------------- device scratch ----------------
__device__ float g_W1t[Zn*Zn];      // W1^T : [k][c_out]
__device__ float g_W2t[Zn*Zn];
__device__ float g_Wut[2*Zn*Hn];    // Wu^T : [k][h]
__device__ float g_m1z[BK*Zn];
__device__ float g_m2z[BK*Zn];
__device__ float g_m[BK*Zn];

// ---------------- f32x2 helpers (Blackwell packed fp32) ----------------
__device__ __forceinline__ unsigned long long ffma2(unsigned long long a,
                                                    unsigned long long b,
                                                    unsigned long long c) {
    unsigned long long d;
    asm("fma.rn.f32x2 %0, %1, %2, %3;" : "=l"(d) : "l"(a), "l"(b), "l"(c));
    return d;
}
__device__ __forceinline__ unsigned long long pack2(float lo, float hi) {
    unsigned long long d;
    asm("mov.b64 %0, {%1, %2};" : "=l"(d) : "f"(lo), "f"(hi));
    return d;
}
__device__ __forceinline__ float2 unpack2(unsigned long long v) {
    float2 r;
    asm("mov.b64 {%0, %1}, %2;" : "=f"(r.x), "=f"(r.y) : "l"(v));
    return r;
}

// ---------------- prep: transpose weights to k-major ----------------
__global__ void prep_kernel(const float* __restrict__ W1,
                            const float* __restrict__ W2,
                            const float* __restrict__ Wu) {
    int stride = gridDim.x * blockDim.x;
    int t0 = blockIdx.x * blockDim.x + threadIdx.x;
    for (int idx = t0; idx < Zn * Zn; idx += stride) {
        int k = idx / Zn, c = idx % Zn;
        g_W1t[idx] = W1[c * Zn + k];
        g_W2t[idx] = W2[c * Zn + k];
    }
    for (int idx = t0; idx < 2 * Zn * Hn; idx += stride) {
        int k = idx / Hn, h = idx % Hn;
        g_Wut[idx] = Wu[h * (2 * Zn) + k];
    }
}

#define MT 32   // M tile per block
#define KC 32   // K chunk

// ---------------- K1: m1z/m2z = z@W^T + b  (grid.y selects W1/W2) --------
__global__ __launch_bounds__(256)
void linear12_kernel(const float* __restrict__ z,
                     const float* __restrict__ b1,
                     const float* __restrict__ b2) {
    __shared__ float Xs[KC][66];      // duplicated pairs: [k][2*m + {0,1}]
    __shared__ float Ws[KC][128];
    const int tid = threadIdx.x;
    const int r0 = blockIdx.x * MT;
    const int wsel = blockIdx.y;
    const float* __restrict__ W    = wsel ? g_W2t : g_W1t;
    const float* __restrict__ bias = wsel ? b2 : b1;
    float* __restrict__ outp       = wsel ? g_m2z : g_m1z;

    const int tn = tid & 31;        // n-quad id
    const int tm = tid >> 5;        // m-quad id (0..7)
    const int n0 = tn * 4;

    const int xr = tid >> 3;        // 0..31: x row in tile
    const int xc = (tid & 7) * 4;   // k offset within chunk

    // prefetch chunk 0
    float4 px = *reinterpret_cast<const float4*>(&z[(size_t)(r0 + xr) * Zn + xc]);
    float4 pw[4];
#pragma unroll
    for (int i = 0; i < 4; i++) {
        int e = tid + i * 256;                 // float4 unit, 1024 total
        int kk = e >> 5, c4 = (e & 31) * 4;
        pw[i] = *reinterpret_cast<const float4*>(&W[kk * Zn + c4]);
    }

    unsigned long long acc[4][2];
#pragma unroll
    for (int m = 0; m < 4; m++) { acc[m][0] = 0ull; acc[m][1] = 0ull; }

    for (int ch = 0; ch < Zn / KC; ch++) {
        {   // store prefetched chunk to smem
            float v[4] = {px.x, px.y, px.z, px.w};
#pragma unroll
            for (int j = 0; j < 4; j++)
                *reinterpret_cast<unsigned long long*>(&Xs[xc + j][xr * 2]) =
                    pack2(v[j], v[j]);
#pragma unroll
            for (int i = 0; i < 4; i++) {
                int e = tid + i * 256;
                int kk = e >> 5, c4 = (e & 31) * 4;
                *reinterpret_cast<float4*>(&Ws[kk][c4]) = pw[i];
            }
        }
        __syncthreads();
        if (ch + 1 < Zn / KC) {     // prefetch next chunk (hidden under compute)
            int kc0 = (ch + 1) * KC;
            px = *reinterpret_cast<const float4*>(&z[(size_t)(r0 + xr) * Zn + kc0 + xc]);
#pragma unroll
            for (int i = 0; i < 4; i++) {
                int e = tid + i * 256;
                int kk = e >> 5, c4 = (e & 31) * 4;
                pw[i] = *reinterpret_cast<const float4*>(&W[(kc0 + kk) * Zn + c4]);
            }
        }
#pragma unroll
        for (int kk = 0; kk < KC; kk++) {
            unsigned long long bp0 = *reinterpret_cast<const unsigned long long*>(&Ws[kk][n0]);
            unsigned long long bp1 = *reinterpret_cast<const unsigned long long*>(&Ws[kk][n0 + 2]);
#pragma unroll
            for (int m = 0; m < 4; m++) {
                unsigned long long a2 =
                    *reinterpret_cast<const unsigned long long*>(&Xs[kk][(tm * 4 + m) * 2]);
                acc[m][0] = ffma2(a2, bp0, acc[m][0]);
                acc[m][1] = ffma2(a2, bp1, acc[m][1]);
            }
        }
        __syncthreads();
    }
    float4 bb = *reinterpret_cast<const float4*>(&bias[n0]);
#pragma unroll
    for (int m = 0; m < 4; m++) {
        float2 lo = unpack2(acc[m][0]);
        float2 hi = unpack2(acc[m][1]);
        float4 o = {lo.x + bb.x, lo.y + bb.y, hi.x + bb.z, hi.y + bb.w};
        *reinterpret_cast<float4*>(&outp[(size_t)(r0 + tm * 4 + m) * Zn + n0]) = o;
    }
}

// ---------------- K2: masked column max + message relu ----------------
// m[b,i,c] = relu(m1z[b,i,c] + max_{j: P[b,j,i]!=0} m2z[b,j,c])
#define IT 32
#define JC 64
__global__ __launch_bounds__(256)
void maxmsg_kernel(const int* __restrict__ P) {
    __shared__ float maskf[Kn][IT];   // 32 KB, {0,-inf}
    __shared__ float m2s[JC][Zn];     // 32 KB
    const int tid = threadIdx.x;
    const int b  = blockIdx.y;
    const int i0 = blockIdx.x * IT;
    const int ig = tid >> 5;          // warp id -> i quad (broadcast mask reads)
    const int cg = tid & 31;          // c quad
    const int c0 = cg * 4;

    // build mask
    const int* Pb = P + (size_t)b * Kn * Kn + i0;
#pragma unroll
    for (int it = 0; it < (Kn * IT) / 256; it++) {
        int e = tid + it * 256;
        int j = e >> 5, ii = e & 31;
        maskf[j][ii] = Pb[(size_t)j * Kn + ii] ? 0.f : -CUDART_INF_F;
    }

    const float* m2base = g_m2z + (size_t)b * Kn * Zn;
    float4 pre[8];
#pragma unroll
    for (int i = 0; i < 8; i++) {
        int e = tid + i * 256;                 // float4 unit, 2048 total
        int jj = e >> 5, c4 = (e & 31) * 4;
        pre[i] = *reinterpret_cast<const float4*>(&m2base[(size_t)jj * Zn + c4]);
    }

    float acc[4][4];
#pragma unroll
    for (int ii = 0; ii < 4; ii++)
#pragma unroll
        for (int cc = 0; cc < 4; cc++) acc[ii][cc] = -CUDART_INF_F;

    for (int jc = 0; jc < Kn / JC; jc++) {
        __syncthreads();   // (iter0: mask ready; later: prev compute done)
#pragma unroll
        for (int i = 0; i < 8; i++) {
            int e = tid + i * 256;
            int jj = e >> 5, c4 = (e & 31) * 4;
            *reinterpret_cast<float4*>(&m2s[jj][c4]) = pre[i];
        }
        __syncthreads();
        if (jc + 1 < Kn / JC) {
#pragma unroll
            for (int i = 0; i < 8; i++) {
                int e = tid + i * 256;
                int jj = e >> 5, c4 = (e & 31) * 4;
                pre[i] = *reinterpret_cast<const float4*>(
                    &m2base[(size_t)((jc + 1) * JC + jj) * Zn + c4]);
            }
        }
#pragma unroll 4
        for (int jj = 0; jj < JC; jj++) {
            float4 v  = *reinterpret_cast<const float4*>(&m2s[jj][c0]);
            float4 mk = *reinterpret_cast<const float4*>(&maskf[jc * JC + jj][ig * 4]);
            float vv[4] = {v.x, v.y, v.z, v.w};
            float mm[4] = {mk.x, mk.y, mk.z, mk.w};
#pragma unroll
            for (int ii = 0; ii < 4; ii++)
#pragma unroll
                for (int cc = 0; cc < 4; cc++)
                    acc[ii][cc] = fmaxf(acc[ii][cc], vv[cc] + mm[ii]);
        }
    }

    const float* m1base = g_m1z + ((size_t)b * Kn + i0 + ig * 4) * Zn + c0;
    float* mout         = g_m   + ((size_t)b * Kn + i0 + ig * 4) * Zn + c0;
#pragma unroll
    for (int ii = 0; ii < 4; ii++) {
        float4 m1 = *reinterpret_cast<const float4*>(&m1base[(size_t)ii * Zn]);
        float4 o;
        o.x = fmaxf(m1.x + acc[ii][0], 0.f);
        o.y = fmaxf(m1.y + acc[ii][1], 0.f);
        o.z = fmaxf(m1.z + acc[ii][2], 0.f);
        o.w = fmaxf(m1.w + acc[ii][3], 0.f);
        *reinterpret_cast<float4*>(&mout[(size_t)ii * Zn]) = o;
    }
}

// ---------------- K3: out = relu([z, m] @ Wu^T + bu), K=256 -------------
__global__ __launch_bounds__(256)
void final_kernel(const float* __restrict__ z,
                  const float* __restrict__ bu,
                  float* __restrict__ out) {
    __shared__ float Xs[KC][66];
    __shared__ float Ws[KC][128];
    const int tid = threadIdx.x;
    const int r0 = blockIdx.x * MT;

    const int tn = tid & 31;
    const int tm = tid >> 5;
    const int n0 = tn * 4;

    const int xr = tid >> 3;
    const int xc = (tid & 7) * 4;

    const float* __restrict__ W = g_Wut;

    // prefetch chunk 0 (from z)
    float4 px = *reinterpret_cast<const float4*>(&z[(size_t)(r0 + xr) * Zn + xc]);
    float4 pw[4];
#pragma unroll
    for (int i = 0; i < 4; i++) {
        int e = tid + i * 256;
        int kk = e >> 5, c4 = (e & 31) * 4;
        pw[i] = *reinterpret_cast<const float4*>(&W[kk * Hn + c4]);
    }

    unsigned long long acc[4][2];
#pragma unroll
    for (int m = 0; m < 4; m++) { acc[m][0] = 0ull; acc[m][1] = 0ull; }

    const int NCH = (2 * Zn) / KC;   // 8 chunks
    for (int ch = 0; ch < NCH; ch++) {
        {
            float v[4] = {px.x, px.y, px.z, px.w};
#pragma unroll
            for (int j = 0; j < 4; j++)
                *reinterpret_cast<unsigned long long*>(&Xs[xc + j][xr * 2]) =
                    pack2(v[j], v[j]);
#pragma unroll
            for (int i = 0; i < 4; i++) {
                int e = tid + i * 256;
                int kk = e >> 5, c4 = (e & 31) * 4;
                *reinterpret_cast<float4*>(&Ws[kk][c4]) = pw[i];
            }
        }
        __syncthreads();
        if (ch + 1 < NCH) {
            int kc0 = (ch + 1) * KC;
            const float* src = (kc0 < Zn)
                ? &z[(size_t)(r0 + xr) * Zn + kc0 + xc]
                : &g_m[(size_t)(r0 + xr) * Zn + (kc0 - Zn) + xc];
            px = *reinterpret_cast<const float4*>(src);
#pragma unroll
            for (int i = 0; i < 4; i++) {
                int e = tid + i * 256;
                int kk = e >> 5, c4 = (e & 31) * 4;
                pw[i] = *reinterpret_cast<const float4*>(&W[(kc0 + kk) * Hn + c4]);
            }
        }
#pragma unroll
        for (int kk = 0; kk < KC; kk++) {
            unsigned long long bp0 = *reinterpret_cast<const unsigned long long*>(&Ws[kk][n0]);
            unsigned long long bp1 = *reinterpret_cast<const unsigned long long*>(&Ws[kk][n0 + 2]);
#pragma unroll
            for (int m = 0; m < 4; m++) {
                unsigned long long a2 =
                    *reinterpret_cast<const unsigned long long*>(&Xs[kk][(tm * 4 + m) * 2]);
                acc[m][0] = ffma2(a2, bp0, acc[m][0]);
                acc[m][1] = ffma2(a2, bp1, acc[m][1]);
            }
        }
        __syncthreads();
    }
    float4 bb = *reinterpret_cast<const float4*>(&bu[n0]);
#pragma unroll
    for (int m = 0; m < 4; m++) {
        float2 lo = unpack2(acc[m][0]);
        float2 hi = unpack2(acc[m][1]);
        float4 o;
        o.x = fmaxf(lo.x + bb.x, 0.f);
        o.y = fmaxf(lo.y + bb.y, 0.f);
        o.z = fmaxf(hi.x + bb.z, 0.f);
        o.w = fmaxf(hi.y + bb.w, 0.f);
        *reinterpret_cast<float4*>(&out[(size_t)(r0 + tm * 4 + m) * Hn + n0]) = o;
    }
}

// --------------------------------------------------------------------------
extern "C" void kernel_launch(void* const* d_in, const int* in_sizes, int n_in,
                              void* d_out, int out_size) {
    const float* z  = (const float*)d_in[0];
    const int*   P  = (const int*)  d_in[1];
    const float* W1 = (const float*)d_in[2];
    const float* b1 = (const float*)d_in[3];
    const float* W2 = (const float*)d_in[4];
    const float* b2 = (const float*)d_in[5];
    const float* Wu = (const float*)d_in[6];
    const float* bu = (const float*)d_in[7];
    float* out = (float*)d_out;

    prep_kernel<<<64, 256>>>(W1, W2, Wu);
    linear12_kernel<<<dim3(BK / MT, 2), 256>>>(z, b1, b2);
    maxmsg_kernel<<<dim3(Kn / IT, Bn), 256>>>(P);
    final_kernel<<<BK / MT, 256>>>(z, bu, out);
}

// round 3
// speedup vs baseline: 1.8539x; 1.0442x over previous
#include <cuda_runtime.h>
#include <math_constants.h>
#include <cstdint>

#define Bn 16
#define Kn 256
#define Zn 128
#define Hn 128
#define BK (Bn*Kn)

typedef unsigned long long ull;

// ---------------- device scratch ----------------
__device__ __align__(16) float g_W1t[Zn*Zn];      // W1^T : [k][c_out]
__device__ __align__(16) float g_W2t[Zn*Zn];
__device__ __align__(16) float g_Wut[2*Zn*Hn];    // Wu^T : [k][h]
__device__ __align__(16) float g_m1z[BK*Zn];
__device__ __align__(16) float g_m2z[BK*Zn];
__device__ __align__(16) float g_m[BK*Zn];

// ---------------- helpers ----------------
__device__ __forceinline__ ull ffma2(ull a, ull b, ull c) {
    ull d;
    asm("fma.rn.f32x2 %0, %1, %2, %3;" : "=l"(d) : "l"(a), "l"(b), "l"(c));
    return d;
}
__device__ __forceinline__ ull pack2(float lo, float hi) {
    ull d;
    asm("mov.b64 %0, {%1, %2};" : "=l"(d) : "f"(lo), "f"(hi));
    return d;
}
__device__ __forceinline__ float2 unpack2(ull v) {
    float2 r;
    asm("mov.b64 {%0, %1}, %2;" : "=f"(r.x), "=f"(r.y) : "l"(v));
    return r;
}
__device__ __forceinline__ float2 add2f(ull a, ull b) {
    float2 r;
    asm("{\n\t.reg .b64 t;\n\tadd.rn.f32x2 t, %2, %3;\n\tmov.b64 {%0,%1}, t;\n\t}"
        : "=f"(r.x), "=f"(r.y) : "l"(a), "l"(b));
    return r;
}
__device__ __forceinline__ uint32_t smem_u32(const void* p) {
    uint32_t a;
    asm("{ .reg .u64 t; cvta.to.shared.u64 t, %1; cvt.u32.u64 %0, t; }" : "=r"(a) : "l"(p));
    return a;
}
__device__ __forceinline__ void cpasync16(uint32_t dst, const void* src) {
    asm volatile("cp.async.cg.shared.global [%0], [%1], 16;" :: "r"(dst), "l"(src) : "memory");
}
#define CP_COMMIT() asm volatile("cp.async.commit_group;" ::: "memory")
#define WAITG(n)    asm volatile("cp.async.wait_group %0;" :: "n"(n) : "memory")
__device__ __forceinline__ void wait_chunk(int ch) {
    switch (ch) {
        case 0: WAITG(3); break;
        case 1: WAITG(2); break;
        case 2: WAITG(1); break;
        default: WAITG(0); break;
    }
}

// ---------------- prep: transpose weights to k-major ----------------
__global__ void prep_kernel(const float* __restrict__ W1,
                            const float* __restrict__ W2,
                            const float* __restrict__ Wu) {
    int stride = gridDim.x * blockDim.x;
    int t0 = blockIdx.x * blockDim.x + threadIdx.x;
    for (int idx = t0; idx < Zn * Zn; idx += stride) {
        int k = idx / Zn, c = idx % Zn;
        g_W1t[idx] = W1[c * Zn + k];
        g_W2t[idx] = W2[c * Zn + k];
    }
    for (int idx = t0; idx < 2 * Zn * Hn; idx += stride) {
        int k = idx / Hn, h = idx % Hn;
        g_Wut[idx] = Wu[h * (2 * Zn) + k];
    }
}

// =========================================================================
// K1: fused m1z = z@W1^T+b1, m2z = z@W2^T+b2.
// Block: 256 thr, tile 32m x 128n x 2mat, full K=128 resident in smem.
// Xs holds duplicated pairs (x,x) for FFMA2 a-operand.
// smem = Xs[128][68] + Ws1[128][128] + Ws2[128][128] = 165,888 B
// =========================================================================
#define L12_SMEM (128*68*4 + 2*128*128*4)
__global__ __launch_bounds__(256)
void linear12_kernel(const float* __restrict__ z,
                     const float* __restrict__ b1,
                     const float* __restrict__ b2) {
    extern __shared__ float sm[];
    float* Xs  = sm;                    // [128][68]
    float* Ws1 = sm + 128 * 68;         // [128][128]
    float* Ws2 = Ws1 + 128 * 128;
    const uint32_t Ws1_a = smem_u32(Ws1);
    const uint32_t Ws2_a = smem_u32(Ws2);

    const int tid = threadIdx.x;
    const int r0  = blockIdx.x * 32;

    // ---- async load of both weight panels, 4 chunk-groups ----
#pragma unroll
    for (int ch = 0; ch < 4; ch++) {
#pragma unroll
        for (int i = 0; i < 8; i++) {
            int e = tid + i * 256;           // 0..2047 float4 units
            int mat = e >> 10;
            int r = e & 1023;
            int kk = r >> 5;
            int c4 = (r & 31) * 4;
            int off = (ch * 32 + kk) * 128 + c4;
            const float* src = (mat ? g_W2t : g_W1t) + off;
            uint32_t dst = (mat ? Ws2_a : Ws1_a) + (uint32_t)off * 4u;
            cpasync16(dst, src);
        }
        CP_COMMIT();
    }

    // ---- z tile -> duplicated pairs in Xs (register transform) ----
    {
        int xr = tid >> 3;
        int xc = (tid & 7) * 4;
#pragma unroll
        for (int ch = 0; ch < 4; ch++) {
            float4 v = *reinterpret_cast<const float4*>(
                &z[(size_t)(r0 + xr) * Zn + ch * 32 + xc]);
            float vv[4] = {v.x, v.y, v.z, v.w};
#pragma unroll
            for (int j = 0; j < 4; j++)
                *reinterpret_cast<ull*>(&Xs[(ch * 32 + xc + j) * 68 + xr * 2]) =
                    pack2(vv[j], vv[j]);
        }
    }

    // ---- compute ----
    const int lane = tid & 31, w = tid >> 5;
    const int mbase = (w >> 2) * 16 + (lane >> 3) * 4;
    const int nbase = (w & 3) * 32 + (lane & 7) * 4;

    ull acc[2][4][2];
#pragma unroll
    for (int t = 0; t < 2; t++)
#pragma unroll
        for (int m = 0; m < 4; m++) { acc[t][m][0] = 0ull; acc[t][m][1] = 0ull; }

    for (int ch = 0; ch < 4; ch++) {
        wait_chunk(ch);
        __syncthreads();
#pragma unroll 8
        for (int kk = ch * 32; kk < ch * 32 + 32; kk++) {
            ulonglong2 a01 = *reinterpret_cast<const ulonglong2*>(&Xs[kk * 68 + mbase * 2]);
            ulonglong2 a23 = *reinterpret_cast<const ulonglong2*>(&Xs[kk * 68 + mbase * 2 + 4]);
            ulonglong2 bw1 = *reinterpret_cast<const ulonglong2*>(&Ws1[kk * 128 + nbase]);
            ulonglong2 bw2 = *reinterpret_cast<const ulonglong2*>(&Ws2[kk * 128 + nbase]);
            ull av[4] = {a01.x, a01.y, a23.x, a23.y};
#pragma unroll
            for (int m = 0; m < 4; m++) {
                acc[0][m][0] = ffma2(av[m], bw1.x, acc[0][m][0]);
                acc[0][m][1] = ffma2(av[m], bw1.y, acc[0][m][1]);
                acc[1][m][0] = ffma2(av[m], bw2.x, acc[1][m][0]);
                acc[1][m][1] = ffma2(av[m], bw2.y, acc[1][m][1]);
            }
        }
    }

    float4 bb1 = *reinterpret_cast<const float4*>(&b1[nbase]);
    float4 bb2 = *reinterpret_cast<const float4*>(&b2[nbase]);
#pragma unroll
    for (int m = 0; m < 4; m++) {
        size_t row = (size_t)(r0 + mbase + m) * Zn + nbase;
        float2 lo = unpack2(acc[0][m][0]);
        float2 hi = unpack2(acc[0][m][1]);
        float4 o1 = {lo.x + bb1.x, lo.y + bb1.y, hi.x + bb1.z, hi.y + bb1.w};
        *reinterpret_cast<float4*>(&g_m1z[row]) = o1;
        lo = unpack2(acc[1][m][0]);
        hi = unpack2(acc[1][m][1]);
        float4 o2 = {lo.x + bb2.x, lo.y + bb2.y, hi.x + bb2.z, hi.y + bb2.w};
        *reinterpret_cast<float4*>(&g_m2z[row]) = o2;
    }
}

// =========================================================================
// K2: m[b,i,c] = relu(m1z[b,i,c] + max_{j: P[b,j,i]!=0} m2z[b,j,c])
// Block: (b, 32-i tile), 256 thr. Whole batch m2z (128KB) + dup-mask (64KB)
// resident in smem. Inner loop: 1 LDS.128(v) + 2 LDS.128(mask,bcast)
// + 8 add.f32x2 (fma pipe) + 16 FMNMX (alu pipe).
// =========================================================================
#define MM_SMEM (256*128*4 + 256*32*8)
__global__ __launch_bounds__(256)
void maxmsg_kernel(const int* __restrict__ P) {
    extern __shared__ float sm[];
    float* m2s = sm;                                  // [256][128]
    ull* mdl = reinterpret_cast<ull*>(sm + 256 * 128); // [256][32] dup {m,m}
    const uint32_t m2s_a = smem_u32(m2s);

    const int tid = threadIdx.x;
    const int b  = blockIdx.y;
    const int i0 = blockIdx.x * 32;

    const float* m2base = g_m2z + (size_t)b * Kn * Zn;
#pragma unroll
    for (int ch = 0; ch < 4; ch++) {
#pragma unroll
        for (int i = 0; i < 8; i++) {
            int e = tid + i * 256;         // 0..2047 float4 units
            int jj = e >> 5;
            int c4 = (e & 31) * 4;
            int off = (ch * 64 + jj) * 128 + c4;
            cpasync16(m2s_a + (uint32_t)off * 4u, m2base + off);
        }
        CP_COMMIT();
    }

    // mask -> dup {0,0} / {-inf,-inf}
    const int* Pb = P + (size_t)b * Kn * Kn + i0;
#pragma unroll
    for (int it = 0; it < 32; it++) {
        int e = tid + it * 256;            // 0..8191
        int j = e >> 5, ii = e & 31;
        mdl[j * 32 + ii] = Pb[(size_t)j * Kn + ii] ? 0ull : 0xFF800000FF800000ull;
    }

    const int ig = tid >> 5;
    const int c0 = (tid & 31) * 4;

    float acc[4][4];
#pragma unroll
    for (int ii = 0; ii < 4; ii++)
#pragma unroll
        for (int cc = 0; cc < 4; cc++) acc[ii][cc] = -CUDART_INF_F;

    for (int ch = 0; ch < 4; ch++) {
        wait_chunk(ch);
        __syncthreads();
#pragma unroll 4
        for (int jj = ch * 64; jj < ch * 64 + 64; jj++) {
            ulonglong2 vv = *reinterpret_cast<const ulonglong2*>(&m2s[jj * 128 + c0]);
            ulonglong2 ma = *reinterpret_cast<const ulonglong2*>(&mdl[jj * 32 + ig * 4]);
            ulonglong2 mb = *reinterpret_cast<const ulonglong2*>(&mdl[jj * 32 + ig * 4 + 2]);
            ull mds[4] = {ma.x, ma.y, mb.x, mb.y};
#pragma unroll
            for (int ii = 0; ii < 4; ii++) {
                float2 t0 = add2f(vv.x, mds[ii]);
                float2 t1 = add2f(vv.y, mds[ii]);
                acc[ii][0] = fmaxf(acc[ii][0], t0.x);
                acc[ii][1] = fmaxf(acc[ii][1], t0.y);
                acc[ii][2] = fmaxf(acc[ii][2], t1.x);
                acc[ii][3] = fmaxf(acc[ii][3], t1.y);
            }
        }
    }

    const float* m1r = g_m1z + ((size_t)b * Kn + i0 + ig * 4) * Zn + c0;
    float* mo        = g_m   + ((size_t)b * Kn + i0 + ig * 4) * Zn + c0;
#pragma unroll
    for (int ii = 0; ii < 4; ii++) {
        float4 m1 = *reinterpret_cast<const float4*>(&m1r[(size_t)ii * Zn]);
        float4 o;
        o.x = fmaxf(m1.x + acc[ii][0], 0.f);
        o.y = fmaxf(m1.y + acc[ii][1], 0.f);
        o.z = fmaxf(m1.z + acc[ii][2], 0.f);
        o.w = fmaxf(m1.w + acc[ii][3], 0.f);
        *reinterpret_cast<float4*>(&mo[(size_t)ii * Zn]) = o;
    }
}

// =========================================================================
// K3: out = relu([z, m] @ Wu^T + bu), K=256, full panel resident.
// smem = Xs[256][68] + Ws[256][128] = 200,704 B
// =========================================================================
#define FIN_SMEM (256*68*4 + 256*128*4)
__global__ __launch_bounds__(256)
void final_kernel(const float* __restrict__ z,
                  const float* __restrict__ bu,
                  float* __restrict__ out) {
    extern __shared__ float sm[];
    float* Xs = sm;                     // [256][68]
    float* Ws = sm + 256 * 68;          // [256][128]
    const uint32_t Ws_a = smem_u32(Ws);

    const int tid = threadIdx.x;
    const int r0  = blockIdx.x * 32;

#pragma unroll
    for (int ch = 0; ch < 4; ch++) {
#pragma unroll
        for (int i = 0; i < 8; i++) {
            int e = tid + i * 256;          // 0..2047 f4 units = 64kk x 128c
            int kk = e >> 5;
            int c4 = (e & 31) * 4;
            int off = (ch * 64 + kk) * 128 + c4;
            cpasync16(Ws_a + (uint32_t)off * 4u, g_Wut + off);
        }
        CP_COMMIT();
    }

    {   // X = [z | m], duplicated pairs
        int xr = tid >> 3;
        int xc = (tid & 7) * 4;
#pragma unroll
        for (int ch = 0; ch < 4; ch++) {
#pragma unroll
            for (int h = 0; h < 2; h++) {
                int kg = ch * 64 + h * 32 + xc;
                const float* src = (kg < Zn)
                    ? &z[(size_t)(r0 + xr) * Zn + kg]
                    : &g_m[(size_t)(r0 + xr) * Zn + (kg - Zn)];
                float4 v = *reinterpret_cast<const float4*>(src);
                float vv[4] = {v.x, v.y, v.z, v.w};
#pragma unroll
                for (int j = 0; j < 4; j++)
                    *reinterpret_cast<ull*>(&Xs[(kg + j) * 68 + xr * 2]) =
                        pack2(vv[j], vv[j]);
            }
        }
    }

    const int lane = tid & 31, w = tid >> 5;
    const int mbase = (w >> 2) * 16 + (lane >> 3) * 4;
    const int nbase = (w & 3) * 32 + (lane & 7) * 4;

    ull acc[4][2];
#pragma unroll
    for (int m = 0; m < 4; m++) { acc[m][0] = 0ull; acc[m][1] = 0ull; }

    for (int ch = 0; ch < 4; ch++) {
        wait_chunk(ch);
        __syncthreads();
#pragma unroll 8
        for (int kk = ch * 64; kk < ch * 64 + 64; kk++) {
            ulonglong2 a01 = *reinterpret_cast<const ulonglong2*>(&Xs[kk * 68 + mbase * 2]);
            ulonglong2 a23 = *reinterpret_cast<const ulonglong2*>(&Xs[kk * 68 + mbase * 2 + 4]);
            ulonglong2 bw  = *reinterpret_cast<const ulonglong2*>(&Ws[kk * 128 + nbase]);
            ull av[4] = {a01.x, a01.y, a23.x, a23.y};
#pragma unroll
            for (int m = 0; m < 4; m++) {
                acc[m][0] = ffma2(av[m], bw.x, acc[m][0]);
                acc[m][1] = ffma2(av[m], bw.y, acc[m][1]);
            }
        }
    }

    float4 bb = *reinterpret_cast<const float4*>(&bu[nbase]);
#pragma unroll
    for (int m = 0; m < 4; m++) {
        float2 lo = unpack2(acc[m][0]);
        float2 hi = unpack2(acc[m][1]);
        float4 o;
        o.x = fmaxf(lo.x + bb.x, 0.f);
        o.y = fmaxf(lo.y + bb.y, 0.f);
        o.z = fmaxf(hi.x + bb.z, 0.f);
        o.w = fmaxf(hi.y + bb.w, 0.f);
        *reinterpret_cast<float4*>(&out[(size_t)(r0 + mbase + m) * Hn + nbase]) = o;
    }
}

// --------------------------------------------------------------------------
extern "C" void kernel_launch(void* const* d_in, const int* in_sizes, int n_in,
                              void* d_out, int out_size) {
    const float* z  = (const float*)d_in[0];
    const int*   P  = (const int*)  d_in[1];
    const float* W1 = (const float*)d_in[2];
    const float* b1 = (const float*)d_in[3];
    const float* W2 = (const float*)d_in[4];
    const float* b2 = (const float*)d_in[5];
    const float* Wu = (const float*)d_in[6];
    const float* bu = (const float*)d_in[7];
    float* out = (float*)d_out;

    cudaFuncSetAttribute(linear12_kernel, cudaFuncAttributeMaxDynamicSharedMemorySize, L12_SMEM);
    cudaFuncSetAttribute(maxmsg_kernel,   cudaFuncAttributeMaxDynamicSharedMemorySize, MM_SMEM);
    cudaFuncSetAttribute(final_kernel,    cudaFuncAttributeMaxDynamicSharedMemorySize, FIN_SMEM);

    prep_kernel<<<64, 256>>>(W1, W2, Wu);
    linear12_kernel<<<BK / 32, 256, L12_SMEM>>>(z, b1, b2);
    maxmsg_kernel<<<dim3(Kn / 32, Bn), 256, MM_SMEM>>>(P);
    final_kernel<<<BK / 32, 256, FIN_SMEM>>>(z, bu, out);
}